// round 16
// baseline (speedup 1.0000x reference)
#include <cuda_runtime.h>
#include <cstdint>

// ---------------------------------------------------------------------------
// WindowAttention fused kernel (fp32 baseline, packed fma.rn.f32x2)
// B_ = 16384 windows, N = 49 tokens, DIM = 128, HEADS = 4, hd = 32, NW = 256
// ---------------------------------------------------------------------------

#define SCALE 0.17677669529663687f   // 32^-0.5

// -------- device scratch (allocation-free: __device__ globals) -------------
__device__ float g_wqkv_t[128 * 384];   // [c][d], q-part prescaled
__device__ float g_bqkv[384];           // bias, q-part prescaled
__device__ float g_wproj_t[128 * 128];  // [c][d]
__device__ float g_biasM[4 * 49 * 49];  // [h][n][m] gathered rel-pos bias

// -------- packed f32x2 helpers ---------------------------------------------
__device__ __forceinline__ unsigned long long pack2(float lo, float hi) {
    unsigned long long r;
    asm("mov.b64 %0, {%1, %2};" : "=l"(r) : "f"(lo), "f"(hi));
    return r;
}
__device__ __forceinline__ float2 unpack2(unsigned long long v) {
    float2 f;
    asm("mov.b64 {%0, %1}, %2;" : "=f"(f.x), "=f"(f.y) : "l"(v));
    return f;
}
#define FMA2(d, a, b, c) \
    asm("fma.rn.f32x2 %0, %1, %2, %3;" : "=l"(d) : "l"(a), "l"(b), "l"(c))

// -------- prep: transposed/prescaled weights + gathered bias ----------------
__global__ void prep_kernel(const float* __restrict__ qkv_w,
                            const float* __restrict__ qkv_b,
                            const float* __restrict__ proj_w,
                            const float* __restrict__ rpb,
                            const int*   __restrict__ rpi) {
    int i = blockIdx.x * blockDim.x + threadIdx.x;
    if (i < 49152) {                       // wqkv_t[c*384 + d] = qkv_w[d*128+c]
        int c = i / 384, d = i % 384;
        float v = qkv_w[d * 128 + c];
        if (d < 128) v *= SCALE;
        g_wqkv_t[i] = v;
    } else if (i < 49536) {                // bias
        int d = i - 49152;
        float v = qkv_b[d];
        if (d < 128) v *= SCALE;
        g_bqkv[d] = v;
    } else if (i < 65920) {                // wproj_t[c*128 + d] = proj_w[d*128+c]
        int j = i - 49536;
        int c = j / 128, d = j % 128;
        g_wproj_t[j] = proj_w[d * 128 + c];
    } else if (i < 75524) {                // biasM[h][n*49+m] = rpb[rpi[n,m], h]
        int j = i - 65920;
        int h = j / 2401, nm = j % 2401;
        g_biasM[j] = rpb[rpi[nm] * 4 + h];
    }
}

// -------- fused window-attention kernel -------------------------------------
// smem: xs[49*128] (reused as attention output O), qkvs[49*390], prows[8*64]
static constexpr int QS = 390;   // qkv row stride (mod 32 == 6 -> <=2-way conflicts, 8B-alignable)
static constexpr int SMEM_FLOATS = 6272 + 49 * QS + 8 * 64;

__global__ __launch_bounds__(256, 2)
void win_attn_kernel(const float* __restrict__ x,
                     const float* __restrict__ mask,
                     const float* __restrict__ proj_b,
                     float* __restrict__ out) {
    extern __shared__ float sm[];
    float* xs    = sm;                 // 49*128 (input x tile, later O tile)
    float* qkvs  = sm + 6272;          // 49*QS  [n][d], d: q 0..127 | k 128..255 | v 256..383
    float* prows = qkvs + 49 * QS;     // per-warp softmax row buffer (64 floats each)

    const int tid  = threadIdx.x;
    const int warp = tid >> 5;
    const int lane = tid & 31;
    const long b   = blockIdx.x;

    // ---- load x tile ----
    {
        const float4* xp = (const float4*)(x + b * 6272);
        float4* xd = (float4*)xs;
        for (int i = tid; i < 1568; i += 256) xd[i] = xp[i];
    }
    __syncthreads();

    // ---- phase 1: QKV = x @ W^T + b  (24 units = 12 d-chunks x 2 n-halves) ----
    for (int u = warp; u < 24; u += 8) {
        const int ch = u >> 1;
        const int n0 = (u & 1) * 24;          // rows 0..24 or 24..48 (row 24 dup, identical)
        const int d  = ch * 32 + lane;
        const float* wcol = g_wqkv_t + d;
        unsigned long long acc[25];
        #pragma unroll
        for (int i = 0; i < 25; i++) acc[i] = 0ULL;

        #pragma unroll 2
        for (int c = 0; c < 128; c += 4) {
            float w0 = wcol[(c + 0) * 384];
            float w1 = wcol[(c + 1) * 384];
            float w2 = wcol[(c + 2) * 384];
            float w3 = wcol[(c + 3) * 384];
            unsigned long long wp0 = pack2(w0, w1);
            unsigned long long wp1 = pack2(w2, w3);
            const float* xr = xs + n0 * 128 + c;
            #pragma unroll
            for (int i = 0; i < 25; i++) {
                ulonglong2 xv = *(const ulonglong2*)(xr + i * 128);
                FMA2(acc[i], xv.x, wp0, acc[i]);
                FMA2(acc[i], xv.y, wp1, acc[i]);
            }
        }
        const float bb = g_bqkv[d];
        #pragma unroll
        for (int i = 0; i < 25; i++) {
            float2 f = unpack2(acc[i]);
            qkvs[(n0 + i) * QS + d] = f.x + f.y + bb;
        }
    }
    __syncthreads();

    // ---- phase 2: per-head attention (2 warps per head) ----
    {
        const int h    = warp >> 1;
        const int wInH = warp & 1;
        const int qoff = h * 32;
        const int koff = 128 + qoff;
        const int voff = 256 + qoff;
        const float* biasp = g_biasM + h * 2401;
        const float* maskp = mask + (long)(blockIdx.x & 255) * 2401;
        float* prow = prows + warp * 64;
        const bool v1 = lane < 17;
        const int m1r = v1 ? (lane + 32) : 48;           // clamp to stay in-bounds
        const float* kbase0 = qkvs + lane * QS + koff;
        const float* kbase1 = qkvs + m1r * QS + koff;
        const float* vcol   = qkvs + voff + lane;

        for (int n = wInH; n < 49; n += 2) {
            const float* qrow = qkvs + n * QS + qoff;
            unsigned long long s0p = 0ULL, s1p = 0ULL;
            #pragma unroll
            for (int j = 0; j < 32; j += 2) {
                unsigned long long qp = *(const unsigned long long*)(qrow + j);
                FMA2(s0p, qp, *(const unsigned long long*)(kbase0 + j), s0p);
                FMA2(s1p, qp, *(const unsigned long long*)(kbase1 + j), s1p);
            }
            float2 a0 = unpack2(s0p), a1 = unpack2(s1p);
            float s0 = a0.x + a0.y;
            float s1 = a1.x + a1.y;
            const int nm = n * 49;
            s0 += biasp[nm + lane] + maskp[nm + lane];
            if (v1) s1 += biasp[nm + lane + 32] + maskp[nm + lane + 32];

            float mx = v1 ? fmaxf(s0, s1) : s0;
            #pragma unroll
            for (int off = 16; off; off >>= 1)
                mx = fmaxf(mx, __shfl_xor_sync(0xffffffffu, mx, off));
            float e0 = __expf(s0 - mx);
            float e1 = v1 ? __expf(s1 - mx) : 0.0f;
            float ssum = e0 + e1;
            #pragma unroll
            for (int off = 16; off; off >>= 1)
                ssum += __shfl_xor_sync(0xffffffffu, ssum, off);
            const float inv = 1.0f / ssum;

            prow[lane] = e0 * inv;
            if (v1) prow[lane + 32] = e1 * inv;
            __syncwarp();

            float ov = 0.0f;
            #pragma unroll
            for (int m = 0; m < 49; m++)
                ov = fmaf(prow[m], vcol[m * QS], ov);
            xs[n * 128 + qoff + lane] = ov;     // O tile reuses xs
            __syncwarp();
        }
    }
    __syncthreads();

    // ---- phase 3: out = O @ Wp^T + bp  (4 d-chunks x 2 n-halves) ----
    {
        const int d  = (warp & 3) * 32 + lane;
        const int n0 = (warp >> 2) * 24;
        const float* wcol = g_wproj_t + d;
        unsigned long long acc[25];
        #pragma unroll
        for (int i = 0; i < 25; i++) acc[i] = 0ULL;

        #pragma unroll 2
        for (int c = 0; c < 128; c += 4) {
            float w0 = wcol[(c + 0) * 128];
            float w1 = wcol[(c + 1) * 128];
            float w2 = wcol[(c + 2) * 128];
            float w3 = wcol[(c + 3) * 128];
            unsigned long long wp0 = pack2(w0, w1);
            unsigned long long wp1 = pack2(w2, w3);
            const float* xr = xs + n0 * 128 + c;
            #pragma unroll
            for (int i = 0; i < 25; i++) {
                ulonglong2 xv = *(const ulonglong2*)(xr + i * 128);
                FMA2(acc[i], xv.x, wp0, acc[i]);
                FMA2(acc[i], xv.y, wp1, acc[i]);
            }
        }
        const float bb = proj_b[d];
        float* op = out + b * 6272 + d;
        #pragma unroll
        for (int i = 0; i < 25; i++) {
            float2 f = unpack2(acc[i]);
            op[(n0 + i) * 128] = f.x + f.y + bb;
        }
    }
}

// -------- launch -------------------------------------------------------------
extern "C" void kernel_launch(void* const* d_in, const int* in_sizes, int n_in,
                              void* d_out, int out_size) {
    const float* x      = (const float*)d_in[0];
    const float* mask   = (const float*)d_in[1];
    const float* qkv_w  = (const float*)d_in[2];
    const float* qkv_b  = (const float*)d_in[3];
    const float* proj_w = (const float*)d_in[4];
    const float* proj_b = (const float*)d_in[5];
    const float* rpb    = (const float*)d_in[6];
    const int*   rpi    = (const int*)d_in[7];
    float* out = (float*)d_out;

    prep_kernel<<<296, 256>>>(qkv_w, qkv_b, proj_w, rpb, rpi);

    const int smemBytes = SMEM_FLOATS * (int)sizeof(float);   // 103,576 B
    cudaFuncSetAttribute(win_attn_kernel,
                         cudaFuncAttributeMaxDynamicSharedMemorySize, smemBytes);
    win_attn_kernel<<<16384, 256, smemBytes>>>(x, mask, proj_b, out);
}

// round 17
// speedup vs baseline: 1.0020x; 1.0020x over previous
#include <cuda_runtime.h>
#include <cstdint>

// ---------------------------------------------------------------------------
// WindowAttention fused kernel (fp32 baseline, packed fma.rn.f32x2)
// B_ = 16384 windows, N = 49 tokens, DIM = 128, HEADS = 4, hd = 32, NW = 256
// ---------------------------------------------------------------------------

#define SCALE 0.17677669529663687f   // 32^-0.5

// -------- device scratch (allocation-free: __device__ globals) -------------
__device__ float g_wqkv_t[128 * 384];   // [c][d], q-part prescaled
__device__ float g_bqkv[384];           // bias, q-part prescaled
__device__ float g_wproj_t[128 * 128];  // [c][d]
__device__ float g_biasM[4 * 49 * 49];  // [h][n][m] gathered rel-pos bias

// -------- packed f32x2 helpers ---------------------------------------------
__device__ __forceinline__ unsigned long long pack2(float lo, float hi) {
    unsigned long long r;
    asm("mov.b64 %0, {%1, %2};" : "=l"(r) : "f"(lo), "f"(hi));
    return r;
}
__device__ __forceinline__ float2 unpack2(unsigned long long v) {
    float2 f;
    asm("mov.b64 {%0, %1}, %2;" : "=f"(f.x), "=f"(f.y) : "l"(v));
    return f;
}
#define FMA2(d, a, b, c) \
    asm("fma.rn.f32x2 %0, %1, %2, %3;" : "=l"(d) : "l"(a), "l"(b), "l"(c))

// -------- prep: transposed/prescaled weights + gathered bias ----------------
__global__ void prep_kernel(const float* __restrict__ qkv_w,
                            const float* __restrict__ qkv_b,
                            const float* __restrict__ proj_w,
                            const float* __restrict__ rpb,
                            const int*   __restrict__ rpi) {
    int i = blockIdx.x * blockDim.x + threadIdx.x;
    if (i < 49152) {                       // wqkv_t[c*384 + d] = qkv_w[d*128+c]
        int c = i / 384, d = i % 384;
        float v = qkv_w[d * 128 + c];
        if (d < 128) v *= SCALE;
        g_wqkv_t[i] = v;
    } else if (i < 49536) {                // bias
        int d = i - 49152;
        float v = qkv_b[d];
        if (d < 128) v *= SCALE;
        g_bqkv[d] = v;
    } else if (i < 65920) {                // wproj_t[c*128 + d] = proj_w[d*128+c]
        int j = i - 49536;
        int c = j / 128, d = j % 128;
        g_wproj_t[j] = proj_w[d * 128 + c];
    } else if (i < 75524) {                // biasM[h][n*49+m] = rpb[rpi[n,m], h]
        int j = i - 65920;
        int h = j / 2401, nm = j % 2401;
        g_biasM[j] = rpb[rpi[nm] * 4 + h];
    }
}

// -------- fused window-attention kernel -------------------------------------
// smem: xs[49*128] (reused as attention output O), qkvs[49*390], prows[8*64]
static constexpr int QS = 390;   // qkv row stride (mod 32 == 6 -> <=2-way conflicts, 8B-alignable)
static constexpr int SMEM_FLOATS = 6272 + 49 * QS + 8 * 64;

__global__ __launch_bounds__(256, 2)
void win_attn_kernel(const float* __restrict__ x,
                     const float* __restrict__ mask,
                     const float* __restrict__ proj_b,
                     float* __restrict__ out) {
    extern __shared__ float sm[];
    float* xs    = sm;                 // 49*128 (input x tile, later O tile)
    float* qkvs  = sm + 6272;          // 49*QS  [n][d], d: q 0..127 | k 128..255 | v 256..383
    float* prows = qkvs + 49 * QS;     // per-warp softmax row buffer (64 floats each)

    const int tid  = threadIdx.x;
    const int warp = tid >> 5;
    const int lane = tid & 31;
    const long b   = blockIdx.x;

    // ---- load x tile ----
    {
        const float4* xp = (const float4*)(x + b * 6272);
        float4* xd = (float4*)xs;
        for (int i = tid; i < 1568; i += 256) xd[i] = xp[i];
    }
    __syncthreads();

    // ---- phase 1: QKV = x @ W^T + b  (24 units = 12 d-chunks x 2 n-halves) ----
    for (int u = warp; u < 24; u += 8) {
        const int ch = u >> 1;
        const int n0 = (u & 1) * 24;          // rows 0..24 or 24..48 (row 24 dup, identical)
        const int d  = ch * 32 + lane;
        const float* wcol = g_wqkv_t + d;
        unsigned long long acc[25];
        #pragma unroll
        for (int i = 0; i < 25; i++) acc[i] = 0ULL;

        #pragma unroll 2
        for (int c = 0; c < 128; c += 4) {
            float w0 = wcol[(c + 0) * 384];
            float w1 = wcol[(c + 1) * 384];
            float w2 = wcol[(c + 2) * 384];
            float w3 = wcol[(c + 3) * 384];
            unsigned long long wp0 = pack2(w0, w1);
            unsigned long long wp1 = pack2(w2, w3);
            const float* xr = xs + n0 * 128 + c;
            #pragma unroll
            for (int i = 0; i < 25; i++) {
                ulonglong2 xv = *(const ulonglong2*)(xr + i * 128);
                FMA2(acc[i], xv.x, wp0, acc[i]);
                FMA2(acc[i], xv.y, wp1, acc[i]);
            }
        }
        const float bb = g_bqkv[d];
        #pragma unroll
        for (int i = 0; i < 25; i++) {
            float2 f = unpack2(acc[i]);
            qkvs[(n0 + i) * QS + d] = f.x + f.y + bb;
        }
    }
    __syncthreads();

    // ---- phase 2: per-head attention (2 warps per head) ----
    {
        const int h    = warp >> 1;
        const int wInH = warp & 1;
        const int qoff = h * 32;
        const int koff = 128 + qoff;
        const int voff = 256 + qoff;
        const float* biasp = g_biasM + h * 2401;
        const float* maskp = mask + (long)(blockIdx.x & 255) * 2401;
        float* prow = prows + warp * 64;
        const bool v1 = lane < 17;
        const int m1r = v1 ? (lane + 32) : 48;           // clamp to stay in-bounds
        const float* kbase0 = qkvs + lane * QS + koff;
        const float* kbase1 = qkvs + m1r * QS + koff;
        const float* vcol   = qkvs + voff + lane;

        for (int n = wInH; n < 49; n += 2) {
            const float* qrow = qkvs + n * QS + qoff;
            unsigned long long s0p = 0ULL, s1p = 0ULL;
            #pragma unroll
            for (int j = 0; j < 32; j += 2) {
                unsigned long long qp = *(const unsigned long long*)(qrow + j);
                FMA2(s0p, qp, *(const unsigned long long*)(kbase0 + j), s0p);
                FMA2(s1p, qp, *(const unsigned long long*)(kbase1 + j), s1p);
            }
            float2 a0 = unpack2(s0p), a1 = unpack2(s1p);
            float s0 = a0.x + a0.y;
            float s1 = a1.x + a1.y;
            const int nm = n * 49;
            s0 += biasp[nm + lane] + maskp[nm + lane];
            if (v1) s1 += biasp[nm + lane + 32] + maskp[nm + lane + 32];

            float mx = v1 ? fmaxf(s0, s1) : s0;
            #pragma unroll
            for (int off = 16; off; off >>= 1)
                mx = fmaxf(mx, __shfl_xor_sync(0xffffffffu, mx, off));
            float e0 = __expf(s0 - mx);
            float e1 = v1 ? __expf(s1 - mx) : 0.0f;
            float ssum = e0 + e1;
            #pragma unroll
            for (int off = 16; off; off >>= 1)
                ssum += __shfl_xor_sync(0xffffffffu, ssum, off);
            const float inv = 1.0f / ssum;

            prow[lane] = e0 * inv;
            if (v1) prow[lane + 32] = e1 * inv;
            __syncwarp();

            float ov = 0.0f;
            #pragma unroll
            for (int m = 0; m < 49; m++)
                ov = fmaf(prow[m], vcol[m * QS], ov);
            xs[n * 128 + qoff + lane] = ov;     // O tile reuses xs
            __syncwarp();
        }
    }
    __syncthreads();

    // ---- phase 3: out = O @ Wp^T + bp  (4 d-chunks x 2 n-halves) ----
    {
        const int d  = (warp & 3) * 32 + lane;
        const int n0 = (warp >> 2) * 24;
        const float* wcol = g_wproj_t + d;
        unsigned long long acc[25];
        #pragma unroll
        for (int i = 0; i < 25; i++) acc[i] = 0ULL;

        #pragma unroll 2
        for (int c = 0; c < 128; c += 4) {
            float w0 = wcol[(c + 0) * 128];
            float w1 = wcol[(c + 1) * 128];
            float w2 = wcol[(c + 2) * 128];
            float w3 = wcol[(c + 3) * 128];
            unsigned long long wp0 = pack2(w0, w1);
            unsigned long long wp1 = pack2(w2, w3);
            const float* xr = xs + n0 * 128 + c;
            #pragma unroll
            for (int i = 0; i < 25; i++) {
                ulonglong2 xv = *(const ulonglong2*)(xr + i * 128);
                FMA2(acc[i], xv.x, wp0, acc[i]);
                FMA2(acc[i], xv.y, wp1, acc[i]);
            }
        }
        const float bb = proj_b[d];
        float* op = out + b * 6272 + d;
        #pragma unroll
        for (int i = 0; i < 25; i++) {
            float2 f = unpack2(acc[i]);
            op[(n0 + i) * 128] = f.x + f.y + bb;
        }
    }
}

// -------- launch -------------------------------------------------------------
extern "C" void kernel_launch(void* const* d_in, const int* in_sizes, int n_in,
                              void* d_out, int out_size) {
    const float* x      = (const float*)d_in[0];
    const float* mask   = (const float*)d_in[1];
    const float* qkv_w  = (const float*)d_in[2];
    const float* qkv_b  = (const float*)d_in[3];
    const float* proj_w = (const float*)d_in[4];
    const float* proj_b = (const float*)d_in[5];
    const float* rpb    = (const float*)d_in[6];
    const int*   rpi    = (const int*)d_in[7];
    float* out = (float*)d_out;

    prep_kernel<<<296, 256>>>(qkv_w, qkv_b, proj_w, rpb, rpi);

    const int smemBytes = SMEM_FLOATS * (int)sizeof(float);   // 103,576 B
    cudaFuncSetAttribute(win_attn_kernel,
                         cudaFuncAttributeMaxDynamicSharedMemorySize, smemBytes);
    win_attn_kernel<<<16384, 256, smemBytes>>>(x, mask, proj_b, out);
}